// round 4
// baseline (speedup 1.0000x reference)
#include <cuda_runtime.h>
#include <cstdint>

// Problem constants (fixed shapes from reference setup_inputs)
#define BZ   4
#define NF   12
#define CC   32
#define HH   256
#define WW   256
#define HW   (HH * WW)          // 65536
#define CHW  (CC * HW)          // 2097152
#define HW4  (HW / 4)           // 16384  (power of 2)
#define CHW4 (CHW / 4)          // 524288 (2^19)

#define BPB      256            // blocks per batch for the MAE reduction
#define K1_THREADS 256

// Scratch (device globals — no allocation allowed). Every slot is fully
// overwritten each launch -> deterministic, graph-replay-safe.
__device__ float g_partial[BZ * NF * BPB];
__device__ int   g_sel[2 * BZ];   // source slice index (f*BZ + b) for each output slice

// ---------------------------------------------------------------------------
// Kernel 1: per-(b, f) MAE partial sums.
// Each block handles a strided chunk of one batch b, keeps 12 focal
// accumulators in registers so x and sal are read ONCE, x_focal read once.
// Traffic: 402 + 33.5 + 1 MB  ->  HBM-bound, ~70 us predicted.
// ---------------------------------------------------------------------------
__global__ __launch_bounds__(K1_THREADS) void mae_partial_kernel(
    const float4* __restrict__ x,     // [BZ][CHW4]
    const float4* __restrict__ xf,    // [NF*BZ][CHW4]
    const float4* __restrict__ sal)   // [BZ][HW4]
{
    const int b   = blockIdx.x >> 8;          // / BPB
    const int blk = blockIdx.x & (BPB - 1);
    int v = blk * K1_THREADS + threadIdx.x;   // float4 index within batch slice
    const int stride = BPB * K1_THREADS;      // 65536

    float acc[NF];
#pragma unroll
    for (int f = 0; f < NF; f++) acc[f] = 0.0f;

    const float4* xb = x   + (size_t)b * CHW4;
    const float4* sb = sal + (size_t)b * HW4;

    // 8 trips total; unroll 2 -> ~28 independent LDG.128 per window for MLP.
#pragma unroll 2
    for (; v < CHW4; v += stride) {
        const float4 xv = xb[v];
        const float4 sv = sb[v & (HW4 - 1)];
#pragma unroll
        for (int f = 0; f < NF; f++) {
            const float4 fv = xf[(size_t)(f * BZ + b) * CHW4 + v];
            acc[f] += fabsf(xv.x - fv.x) * sv.x
                    + fabsf(xv.y - fv.y) * sv.y
                    + fabsf(xv.z - fv.z) * sv.z
                    + fabsf(xv.w - fv.w) * sv.w;
        }
    }

    // Warp tree-reduce each accumulator (deterministic), then cross-warp via smem.
#pragma unroll
    for (int f = 0; f < NF; f++) {
#pragma unroll
        for (int o = 16; o > 0; o >>= 1)
            acc[f] += __shfl_xor_sync(0xFFFFFFFFu, acc[f], o);
    }

    __shared__ float s[NF][K1_THREADS / 32];
    const int w = threadIdx.x >> 5;
    const int l = threadIdx.x & 31;
    if (l == 0) {
#pragma unroll
        for (int f = 0; f < NF; f++) s[f][w] = acc[f];
    }
    __syncthreads();

    if (threadIdx.x < NF) {
        float t = 0.0f;
#pragma unroll
        for (int ww = 0; ww < K1_THREADS / 32; ww++) t += s[threadIdx.x][ww];
        g_partial[((b * NF) + threadIdx.x) * BPB + blk] = t;
    }
}

// ---------------------------------------------------------------------------
// Kernel 2: reduce partials -> mae[b][f] (double accumulation, fixed order),
// then per-batch pair argmax with row-major first-max semantics.
// ---------------------------------------------------------------------------
__global__ void select_kernel()
{
    __shared__ float mae[BZ * NF];
    const int tid = threadIdx.x;

    if (tid < BZ * NF) {
        double t = 0.0;
        const float* p = &g_partial[tid * BPB];
        for (int k = 0; k < BPB; k++) t += (double)p[k];
        mae[tid] = (float)(t / (double)CHW);
    }
    __syncthreads();

    if (tid < BZ) {
        const float* m = &mae[tid * NF];
        float best = -1.0f;
        int bi = 0, bj = 0;
        for (int i = 0; i < NF; i++) {
            for (int j = i + 1; j < NF; j++) {
                const float d = m[i] - m[j];
                const float v = 0.5f * d * d;
                if (v > best) { best = v; bi = i; bj = j; }  // strict > keeps first max
            }
        }
        if (!(best > 0.0f)) { bi = 0; bj = 0; }              // torch keeps [0,0] unless > 0
        g_sel[tid]      = bi * BZ + tid;   // g1 source slice in x_focal
        g_sel[tid + BZ] = bj * BZ + tid;   // g2 source slice
    }
}

// ---------------------------------------------------------------------------
// Kernel 3: gather copy, float4 vectorized, 4 elements/thread for MLP.
// 64 MB read + 64 MB write -> ~20 us.
// ---------------------------------------------------------------------------
#define G_ELEMS (2 * BZ * CHW4)     // 4194304 float4s
#define G_PER_T 4

__global__ __launch_bounds__(256) void gather_kernel(
    const float4* __restrict__ xf, float4* __restrict__ out)
{
    const int base = (blockIdx.x * 256 + threadIdx.x) * G_PER_T;
#pragma unroll
    for (int k = 0; k < G_PER_T; k++) {
        const int v      = base + k;
        const int slice  = v >> 19;                 // / CHW4
        const int within = v & (CHW4 - 1);
        out[v] = xf[(size_t)g_sel[slice] * CHW4 + within];
    }
}

// ---------------------------------------------------------------------------
extern "C" void kernel_launch(void* const* d_in, const int* in_sizes, int n_in,
                              void* d_out, int out_size)
{
    const float4* x   = (const float4*)d_in[0];   // [4,32,256,256]
    const float4* xf  = (const float4*)d_in[1];   // [48,32,256,256]
    const float4* sal = (const float4*)d_in[2];   // [4,1,256,256]
    float4* out = (float4*)d_out;                 // [8,32,256,256]

    (void)in_sizes; (void)n_in; (void)out_size;

    mae_partial_kernel<<<BZ * BPB, K1_THREADS>>>(x, xf, sal);
    select_kernel<<<1, 64>>>();
    gather_kernel<<<G_ELEMS / (256 * G_PER_T), 256>>>(xf, out);
}

// round 12
// speedup vs baseline: 1.2198x; 1.2198x over previous
#include <cuda_runtime.h>
#include <cstdint>

// Problem constants (fixed shapes from reference setup_inputs)
#define BZ   4
#define NF   12
#define CHW  2097152            // 32*256*256
#define HW4  16384              // 65536/4 (power of 2)
#define CHW4 524288             // 2^19 float4s per slice

#define BPB      148            // blocks per batch: 4*148 = 592 = one full wave @ occ 4
#define K1_GRID  (BZ * BPB)     // 592
#define K1_THREADS 256
#define K1_STRIDE  (BPB * K1_THREADS)   // 37888

// Scratch (device globals — no allocation allowed). Deterministic, replay-safe:
// g_partial/g_sel fully overwritten each launch; g_count returns to 0 at the
// end of every launch (last block resets it).
__device__ float g_partial[BZ * NF * BPB];
__device__ int   g_sel[2 * BZ];
__device__ int   g_count = 0;

// ---------------------------------------------------------------------------
// Kernel 1: per-(b,f) MAE partial sums + fused selection in the last block.
// 12 focal accumulators in registers -> x, sal read once, x_focal read once.
// Grid 592 = exactly 148 SMs x 4 blocks: single wave, no tail imbalance.
// ---------------------------------------------------------------------------
__global__ __launch_bounds__(K1_THREADS) void mae_select_kernel(
    const float4* __restrict__ x,     // [BZ][CHW4]
    const float4* __restrict__ xf,    // [NF*BZ][CHW4]
    const float4* __restrict__ sal)   // [BZ][HW4]
{
    const int b   = blockIdx.x / BPB;
    const int blk = blockIdx.x % BPB;
    int v = blk * K1_THREADS + threadIdx.x;

    float acc[NF];
#pragma unroll
    for (int f = 0; f < NF; f++) acc[f] = 0.0f;

    const float4* xb = x   + (size_t)b * CHW4;
    const float4* sb = sal + (size_t)b * HW4;

#pragma unroll 2
    for (; v < CHW4; v += K1_STRIDE) {
        const float4 xv = xb[v];
        const float4 sv = sb[v & (HW4 - 1)];
#pragma unroll
        for (int f = 0; f < NF; f++) {
            const float4 fv = xf[(size_t)(f * BZ + b) * CHW4 + v];
            acc[f] += fabsf(xv.x - fv.x) * sv.x
                    + fabsf(xv.y - fv.y) * sv.y
                    + fabsf(xv.z - fv.z) * sv.z
                    + fabsf(xv.w - fv.w) * sv.w;
        }
    }

    // Deterministic block reduction: warp shfl tree, then cross-warp via smem.
#pragma unroll
    for (int f = 0; f < NF; f++) {
#pragma unroll
        for (int o = 16; o > 0; o >>= 1)
            acc[f] += __shfl_xor_sync(0xFFFFFFFFu, acc[f], o);
    }

    __shared__ float s[NF][K1_THREADS / 32];
    const int w = threadIdx.x >> 5;
    const int l = threadIdx.x & 31;
    if (l == 0) {
#pragma unroll
        for (int f = 0; f < NF; f++) s[f][w] = acc[f];
    }
    __syncthreads();

    if (threadIdx.x < NF) {
        float t = 0.0f;
#pragma unroll
        for (int ww = 0; ww < K1_THREADS / 32; ww++) t += s[threadIdx.x][ww];
        g_partial[((b * NF) + threadIdx.x) * BPB + blk] = t;
    }

    // --- last-block selection (threadFenceReduction pattern) ---
    __shared__ bool is_last;
    __threadfence();                      // publish partials before ticket
    if (threadIdx.x == 0) {
        const int ticket = atomicAdd(&g_count, 1);
        is_last = (ticket == K1_GRID - 1);
    }
    __syncthreads();
    if (!is_last) return;
    __threadfence();                      // acquire: see all published partials

    // Warp-parallel reduce of 148 partials per (b,f): 8 warps x 6 entries.
    __shared__ float mae[BZ * NF];
    {
        const int warp = threadIdx.x >> 5;
        const int lane = threadIdx.x & 31;
#pragma unroll
        for (int e6 = 0; e6 < 6; e6++) {
            const int e = warp * 6 + e6;          // 0..47
            float t = 0.0f;
#pragma unroll
            for (int k = 0; k < 5; k++) {         // 148 = 4*32 + 20
                const int idx = lane + 32 * k;
                if (idx < BPB) t += g_partial[e * BPB + idx];
            }
#pragma unroll
            for (int o = 16; o > 0; o >>= 1)
                t += __shfl_xor_sync(0xFFFFFFFFu, t, o);
            if (lane == 0) mae[e] = t / (float)CHW;
        }
    }
    __syncthreads();

    if (threadIdx.x < BZ) {
        const int bb = threadIdx.x;
        const float* m = &mae[bb * NF];
        float best = -1.0f;
        int bi = 0, bj = 0;
        for (int i = 0; i < NF; i++) {
            for (int j = i + 1; j < NF; j++) {
                const float d = m[i] - m[j];
                const float vv = 0.5f * d * d;
                if (vv > best) { best = vv; bi = i; bj = j; }   // first max wins
            }
        }
        if (!(best > 0.0f)) { bi = 0; bj = 0; }   // keep [0,0] unless strictly > 0
        g_sel[bb]      = bi * BZ + bb;
        g_sel[bb + BZ] = bj * BZ + bb;
    }
    if (threadIdx.x == 0) g_count = 0;    // reset for next graph replay
}

// ---------------------------------------------------------------------------
// Kernel 2: gather copy. 2048 float4s per block (never straddles a slice
// since 2048 | 2^19) -> one uniform g_sel load per block. 8 float4/thread.
// ---------------------------------------------------------------------------
#define G_BLK_ELEMS 2048
#define G_GRID      ((2 * BZ * CHW4) / G_BLK_ELEMS)   // 2048 blocks

__global__ __launch_bounds__(256) void gather_kernel(
    const float4* __restrict__ xf, float4* __restrict__ out)
{
    const int slice = blockIdx.x >> 8;                 // (blockIdx*2048) / 2^19
    const float4* src = xf + (size_t)g_sel[slice] * CHW4
                           + ((size_t)blockIdx.x * G_BLK_ELEMS & (CHW4 - 1));
    float4* dst = out + (size_t)blockIdx.x * G_BLK_ELEMS;

    const int t = threadIdx.x;
#pragma unroll
    for (int k = 0; k < G_BLK_ELEMS / 256; k++)
        dst[t + k * 256] = src[t + k * 256];
}

// ---------------------------------------------------------------------------
extern "C" void kernel_launch(void* const* d_in, const int* in_sizes, int n_in,
                              void* d_out, int out_size)
{
    const float4* x   = (const float4*)d_in[0];   // [4,32,256,256]
    const float4* xf  = (const float4*)d_in[1];   // [48,32,256,256]
    const float4* sal = (const float4*)d_in[2];   // [4,1,256,256]
    float4* out = (float4*)d_out;                 // [8,32,256,256]

    (void)in_sizes; (void)n_in; (void)out_size;

    mae_select_kernel<<<K1_GRID, K1_THREADS>>>(x, xf, sal);
    gather_kernel<<<G_GRID, 256>>>(xf, out);
}